// round 1
// baseline (speedup 1.0000x reference)
#include <cuda_runtime.h>

// Combined gate: product of three 16-element dot products' sign predicates.
__device__ float g_flag;

#define STATE_DIM 16

__global__ void compute_flag_kernel(const float* __restrict__ Bs, const float* __restrict__ Cs,
                                    const float* __restrict__ Ba, const float* __restrict__ Ca,
                                    const float* __restrict__ Be, const float* __restrict__ Ce) {
    float k1 = 0.f, k2 = 0.f, k3 = 0.f;
#pragma unroll
    for (int s = 0; s < STATE_DIM; ++s) {
        k1 += Bs[s] * Cs[s];   // B is (16,1), C is (1,16): both contiguous 16 floats
        k2 += Ba[s] * Ca[s];
        k3 += Be[s] * Ce[s];
    }
    g_flag = (k1 > 0.f && k2 > 0.f && k3 > 0.f) ? 1.0f : 0.0f;
}

// out = x * flag, vectorized float4. N is a multiple of 1024 so float4 exact.
__global__ void masked_copy_kernel(const float4* __restrict__ x, float4* __restrict__ out,
                                   int n_vec) {
    const float f = g_flag;
    int i = blockIdx.x * blockDim.x + threadIdx.x;
    if (i < n_vec) {
        float4 v = x[i];
        v.x *= f; v.y *= f; v.z *= f; v.w *= f;
        out[i] = v;
    }
}

extern "C" void kernel_launch(void* const* d_in, const int* in_sizes, int n_in,
                              void* d_out, int out_size) {
    // metadata order:
    // 0: incoming_spikes (4096*1024 f32)
    // 1: A_sensory  2: B_sensory  3: C_sensory
    // 4: A_association 5: B_association 6: C_association
    // 7: A_executive 8: B_executive 9: C_executive
    const float* x  = (const float*)d_in[0];
    const float* Bs = (const float*)d_in[2];
    const float* Cs = (const float*)d_in[3];
    const float* Ba = (const float*)d_in[5];
    const float* Ca = (const float*)d_in[6];
    const float* Be = (const float*)d_in[8];
    const float* Ce = (const float*)d_in[9];
    float* out = (float*)d_out;

    compute_flag_kernel<<<1, 1>>>(Bs, Cs, Ba, Ca, Be, Ce);

    int n_vec = out_size / 4;               // out_size = 4096*1024, divisible by 4
    int threads = 256;
    int blocks = (n_vec + threads - 1) / threads;
    masked_copy_kernel<<<blocks, threads>>>((const float4*)x, (float4*)out, n_vec);
}

// round 2
// speedup vs baseline: 1.2403x; 1.2403x over previous
#include <cuda_runtime.h>

#define STATE_DIM 16

// One fused kernel: per-block flag compute (thread 0, L2-broadcast-hot) +
// 4x float4 masked copy per thread for MLP=4.
__global__ void fused_masked_copy_kernel(const float4* __restrict__ x,
                                         float4* __restrict__ out,
                                         const float* __restrict__ Bs, const float* __restrict__ Cs,
                                         const float* __restrict__ Ba, const float* __restrict__ Ca,
                                         const float* __restrict__ Be, const float* __restrict__ Ce,
                                         int n_vec) {
    __shared__ float sflag;
    if (threadIdx.x == 0) {
        float k1 = 0.f, k2 = 0.f, k3 = 0.f;
#pragma unroll
        for (int s = 0; s < STATE_DIM; ++s) {
            k1 += Bs[s] * Cs[s];
            k2 += Ba[s] * Ca[s];
            k3 += Be[s] * Ce[s];
        }
        sflag = (k1 > 0.f && k2 > 0.f && k3 > 0.f) ? 1.0f : 0.0f;
    }
    __syncthreads();
    const float f = sflag;

    // Each block handles 256 threads * 4 float4 = 1024 float4, coalesced.
    int base = blockIdx.x * (blockDim.x * 4) + threadIdx.x;
    int stride = blockDim.x;

    if (base + 3 * stride < n_vec) {
        // Fast path: 4 independent loads issued back-to-back (MLP=4).
        float4 v0 = x[base];
        float4 v1 = x[base + stride];
        float4 v2 = x[base + 2 * stride];
        float4 v3 = x[base + 3 * stride];
        v0.x *= f; v0.y *= f; v0.z *= f; v0.w *= f;
        v1.x *= f; v1.y *= f; v1.z *= f; v1.w *= f;
        v2.x *= f; v2.y *= f; v2.z *= f; v2.w *= f;
        v3.x *= f; v3.y *= f; v3.z *= f; v3.w *= f;
        out[base]              = v0;
        out[base + stride]     = v1;
        out[base + 2 * stride] = v2;
        out[base + 3 * stride] = v3;
    } else {
#pragma unroll
        for (int k = 0; k < 4; ++k) {
            int i = base + k * stride;
            if (i < n_vec) {
                float4 v = x[i];
                v.x *= f; v.y *= f; v.z *= f; v.w *= f;
                out[i] = v;
            }
        }
    }
}

extern "C" void kernel_launch(void* const* d_in, const int* in_sizes, int n_in,
                              void* d_out, int out_size) {
    // metadata order:
    // 0: incoming_spikes (4096*1024 f32)
    // 1: A_sensory  2: B_sensory  3: C_sensory
    // 4: A_association 5: B_association 6: C_association
    // 7: A_executive 8: B_executive 9: C_executive
    const float* x  = (const float*)d_in[0];
    const float* Bs = (const float*)d_in[2];
    const float* Cs = (const float*)d_in[3];
    const float* Ba = (const float*)d_in[5];
    const float* Ca = (const float*)d_in[6];
    const float* Be = (const float*)d_in[8];
    const float* Ce = (const float*)d_in[9];
    float* out = (float*)d_out;

    int n_vec = out_size / 4;                      // float4 count; out_size divisible by 4
    int threads = 256;
    int per_block = threads * 4;                   // 1024 float4 per block
    int blocks = (n_vec + per_block - 1) / per_block;

    fused_masked_copy_kernel<<<blocks, threads>>>((const float4*)x, (float4*)out,
                                                  Bs, Cs, Ba, Ca, Be, Ce, n_vec);
}